// round 9
// baseline (speedup 1.0000x reference)
#include <cuda_runtime.h>
#include <cuda_fp16.h>
#include <math.h>
#include <stdint.h>

// Shapes (fixed): B=32, T=128, V=32000, E=512, H=1024, 4H=4096
#define BB 32
#define TT 128
#define VV 32000
#define EE 512
#define HH 1024
#define GG 4096
#define MM 4096   // T*B rows

// ------------------------- static device scratch ---------------------------
__device__ float  g_xz[(size_t)MM * GG];        // emb[X]@W + b  (64 MB)
__device__ float  g_h[2][BB * HH];              // h ping-pong
__device__ __half g_hs_h[(size_t)MM * HH];      // hs fp16 (8 MB) — proj A
__device__ __half g_wdt_h[(size_t)VV * HH];     // Wd^T fp16 [V][K] (64 MB)
__device__ unsigned g_bar;                      // persistent-kernel barrier

__device__ __forceinline__ float sigm(float x) { return 1.0f / (1.0f + expf(-x)); }

__device__ __forceinline__ uint32_t smem_u32(const void* p) {
    uint32_t a;
    asm("{ .reg .u64 t; cvta.to.shared.u64 t, %1; cvt.u32.u64 %0, t; }"
        : "=r"(a) : "l"(p));
    return a;
}
__device__ __forceinline__ void cpa16(uint32_t d, const void* s) {
    asm volatile("cp.async.cg.shared.global [%0], [%1], 16;" :: "r"(d), "l"(s));
}
#define SWZ(x) ((x) ^ (((x) >> 3) & 0x70))

// ---------------------------------------------------------------------------
// Kernel 0: zero the persistent barrier counter
// ---------------------------------------------------------------------------
__global__ void init_bar_kernel() { g_bar = 0u; }

// ---------------------------------------------------------------------------
// Kernel 1: Xz = gather(emb, X) @ W + b      M=4096, N=4096, K=512  (fp32)
// ---------------------------------------------------------------------------
__global__ void __launch_bounds__(256) gemm_xz_kernel(
    const int* __restrict__ X, const float* __restrict__ emb,
    const float* __restrict__ W, const float* __restrict__ bias)
{
    __shared__ float As[8][132];
    __shared__ float Bs[8][128];
    __shared__ int   sidx[128];

    const int tid = threadIdx.x;
    const int rowbase = blockIdx.y * 128;
    const int nbase   = blockIdx.x * 128;

    if (tid < 128) {
        int r = rowbase + tid;
        int t = r >> 5, b = r & 31;
        sidx[tid] = X[b * TT + t];
    }
    __syncthreads();

    const int arow = tid >> 1;
    const int acol = (tid & 1) * 4;
    const int brow = tid >> 5;
    const int bcol = (tid & 31) * 4;
    const int ty = tid >> 4;
    const int tx = tid & 15;

    float acc[8][8];
#pragma unroll
    for (int i = 0; i < 8; i++)
#pragma unroll
        for (int j = 0; j < 8; j++) acc[i][j] = 0.0f;

    const int erow = sidx[arow];

    for (int k0 = 0; k0 < EE; k0 += 8) {
        float4 av = *(const float4*)(emb + (size_t)erow * EE + k0 + acol);
        As[acol + 0][arow] = av.x;
        As[acol + 1][arow] = av.y;
        As[acol + 2][arow] = av.z;
        As[acol + 3][arow] = av.w;
        *(float4*)&Bs[brow][bcol] =
            *(const float4*)(W + (size_t)(k0 + brow) * GG + nbase + bcol);
        __syncthreads();

#pragma unroll
        for (int kk = 0; kk < 8; kk++) {
            float ar[8], br[8];
#pragma unroll
            for (int i = 0; i < 8; i++) ar[i] = As[kk][ty * 8 + i];
#pragma unroll
            for (int j = 0; j < 8; j++) br[j] = Bs[kk][tx * 8 + j];
#pragma unroll
            for (int i = 0; i < 8; i++)
#pragma unroll
                for (int j = 0; j < 8; j++) acc[i][j] = fmaf(ar[i], br[j], acc[i][j]);
        }
        __syncthreads();
    }

    float bv[8];
#pragma unroll
    for (int j = 0; j < 8; j++) bv[j] = bias[nbase + tx * 8 + j];

#pragma unroll
    for (int i = 0; i < 8; i++) {
        int row = rowbase + ty * 8 + i;
        float* o = g_xz + (size_t)row * GG + nbase + tx * 8;
#pragma unroll
        for (int j = 0; j < 8; j++) o[j] = acc[i][j] + bv[j];
    }
}

// ---------------------------------------------------------------------------
// Kernel 2: persistent LSTM. 128 CTAs (1/SM, all resident), 128 threads.
//   CTA owns j-octet jbase..jbase+7 (x 4 gates = 32 of the 4096 cols).
//   U slice staged once in smem (128 KB), gate-interleaved [k][jl*4+g].
//   Per step: stage h chunks (128 k), 2-way K-split accumulate, smem-reduce,
//   gate math with c in registers, h to global (stcg), hs to fp16.
//   Steps separated by a global atomic-counter barrier.
// Dyn smem: su 131072 + sh 2*32*129*4=33024 + red 4096 = 168192 B.
// ---------------------------------------------------------------------------
__global__ void __launch_bounds__(128, 1) lstm_persistent_kernel(
    const float* __restrict__ h0, const float* __restrict__ c0,
    const float* __restrict__ U)
{
    extern __shared__ float dsm[];
    float* su  = dsm;                       // [1024][32]
    float* sh  = dsm + 1024 * 32;           // [2][32][129]
    float* red = sh + 2 * 32 * 129;         // [64][16]

    const int tid = threadIdx.x;
    const int ks  = tid >> 6;               // 0..1  K-split
    const int pos = tid & 63;
    const int bg  = pos >> 3;               // 0..7  (b = 4*bg + bi)
    const int jl  = pos & 7;                // 0..7
    const int jbase = blockIdx.x * 8;

    // stage U once: su[k][c], c = jl*4 + g  ->  U[k][g*1024 + jbase + jl]
    for (int i = tid; i < 1024 * 32; i += 128) {
        int k = i >> 5, c = i & 31;
        int g = c & 3, j2 = c >> 2;
        su[k * 32 + c] = U[(size_t)k * GG + g * 1024 + jbase + j2];
    }

    float creg[4];
#pragma unroll
    for (int bi = 0; bi < 4; bi++)
        creg[bi] = c0[(bg * 4 + bi) * HH + jbase + jl];   // only ks==0 uses these

    __syncthreads();

    for (int t = 0; t < TT; t++) {
        const float* hprev = (t == 0) ? h0 : g_h[(t - 1) & 1];

        float acc[4][4];
#pragma unroll
        for (int bi = 0; bi < 4; bi++)
#pragma unroll
            for (int g = 0; g < 4; g++) acc[bi][g] = 0.0f;

        for (int cc = 0; cc < 4; cc++) {
            __syncthreads();
            // stage sh[r][b][kk] = hprev[b][r*512 + cc*128 + kk]
            for (int i = tid; i < 2 * 32 * 128; i += 128) {
                int r = i >> 12, rem = i & 4095;
                int b = rem >> 7, kk = rem & 127;
                sh[(r * 32 + b) * 129 + kk] =
                    __ldcg(&hprev[b * HH + r * 512 + cc * 128 + kk]);
            }
            __syncthreads();

            const float* shk = sh + (ks * 32) * 129;
            const float* suk = su + (size_t)(ks * 512 + cc * 128) * 32;
#pragma unroll 4
            for (int kk = 0; kk < 128; kk++) {
                const float4 ug = *(const float4*)(suk + kk * 32 + (jl << 2));
                float hv0 = shk[(bg * 4 + 0) * 129 + kk];
                float hv1 = shk[(bg * 4 + 1) * 129 + kk];
                float hv2 = shk[(bg * 4 + 2) * 129 + kk];
                float hv3 = shk[(bg * 4 + 3) * 129 + kk];
                acc[0][0] = fmaf(hv0, ug.x, acc[0][0]);
                acc[0][1] = fmaf(hv0, ug.y, acc[0][1]);
                acc[0][2] = fmaf(hv0, ug.z, acc[0][2]);
                acc[0][3] = fmaf(hv0, ug.w, acc[0][3]);
                acc[1][0] = fmaf(hv1, ug.x, acc[1][0]);
                acc[1][1] = fmaf(hv1, ug.y, acc[1][1]);
                acc[1][2] = fmaf(hv1, ug.z, acc[1][2]);
                acc[1][3] = fmaf(hv1, ug.w, acc[1][3]);
                acc[2][0] = fmaf(hv2, ug.x, acc[2][0]);
                acc[2][1] = fmaf(hv2, ug.y, acc[2][1]);
                acc[2][2] = fmaf(hv2, ug.z, acc[2][2]);
                acc[2][3] = fmaf(hv2, ug.w, acc[2][3]);
                acc[3][0] = fmaf(hv3, ug.x, acc[3][0]);
                acc[3][1] = fmaf(hv3, ug.y, acc[3][1]);
                acc[3][2] = fmaf(hv3, ug.z, acc[3][2]);
                acc[3][3] = fmaf(hv3, ug.w, acc[3][3]);
            }
        }

        if (ks == 1) {
#pragma unroll
            for (int bi = 0; bi < 4; bi++)
#pragma unroll
                for (int g = 0; g < 4; g++)
                    red[pos * 16 + bi * 4 + g] = acc[bi][g];
        }
        __syncthreads();

        if (ks == 0) {
            const float* xzr = g_xz + (size_t)t * BB * GG;
            float* hnext = g_h[t & 1];
            const int j = jbase + jl;
#pragma unroll
            for (int bi = 0; bi < 4; bi++) {
                int b = bg * 4 + bi;
                const float* xb = xzr + (size_t)b * GG;
                float zi = acc[bi][0] + red[pos * 16 + bi * 4 + 0] + xb[j];
                float zf = acc[bi][1] + red[pos * 16 + bi * 4 + 1] + xb[HH + j];
                float zg = acc[bi][2] + red[pos * 16 + bi * 4 + 2] + xb[2 * HH + j];
                float zo = acc[bi][3] + red[pos * 16 + bi * 4 + 3] + xb[3 * HH + j];
                float cn = sigm(zf) * creg[bi] + sigm(zi) * tanhf(zg);
                float hn = sigm(zo) * tanhf(cn);
                creg[bi] = cn;
                __stcg(&hnext[b * HH + j], hn);
                g_hs_h[(size_t)(t * BB + b) * HH + j] = __float2half(hn);
            }
        }

        __threadfence();
        __syncthreads();
        if (tid == 0) {
            atomicAdd(&g_bar, 1u);
            unsigned target = 128u * (unsigned)(t + 1);
            while (atomicAdd(&g_bar, 0u) < target) { }
        }
        __syncthreads();
    }
}

// ---------------------------------------------------------------------------
// Kernel 3: Wd [K=1024][V] -> Wd^T fp16 [V][K]  (transpose + convert)
// ---------------------------------------------------------------------------
__global__ void __launch_bounds__(256) wd_split_kernel(const float* __restrict__ Wd)
{
    __shared__ float t[32][33];
    const int v0 = blockIdx.x * 32;
    const int k0 = blockIdx.y * 32;
    const int tx = threadIdx.x & 31;
    const int ty0 = threadIdx.x >> 5;

#pragma unroll
    for (int ty = ty0; ty < 32; ty += 8)
        t[ty][tx] = Wd[(size_t)(k0 + ty) * VV + v0 + tx];
    __syncthreads();

#pragma unroll
    for (int ty = ty0; ty < 32; ty += 8)
        g_wdt_h[(size_t)(v0 + ty) * HH + k0 + tx] = __float2half(t[tx][ty]);
}

// ---------------------------------------------------------------------------
// Kernel 4: projection via mma.sync (HMMA fp16, fp32 accum) + fused BN.
//   out = BN( hs @ Wd + bd ).  M=4096, N=32000, K=1024.
//   CTA 128x128, 8 warps (warp 32m x 64n), K-chunks of 64, cp.async 2-stage.
// Dyn smem: 2 bufs x (A 16K + B 16K) = 65536, + sc/sf -> 66560 B.
// ---------------------------------------------------------------------------
__global__ void __launch_bounds__(256, 1) proj_mma_kernel(
    const float* __restrict__ bd, const float* __restrict__ gamma,
    const float* __restrict__ beta, const float* __restrict__ mmean,
    const float* __restrict__ mvar, float* __restrict__ out)
{
    extern __shared__ char smem[];
    const int tid = threadIdx.x;
    const int wid = tid >> 5, l = tid & 31;
    const int wr = wid & 3, wc = wid >> 2;
    const int m0 = blockIdx.y << 7;
    const int n0 = blockIdx.x << 7;

    float* sc = (float*)(smem + 65536);
    float* sf = (float*)(smem + 66048);
    if (tid < 128) {
        int n = n0 + tid;
        float iv = gamma[n] * rsqrtf(mvar[n] + 1e-3f);
        sc[tid] = iv;
        sf[tid] = beta[n] + (bd[n] - mmean[n]) * iv;
    }

    const uint32_t sb = smem_u32(smem);
    const __half* Ag = g_hs_h  + (size_t)m0 * HH;
    const __half* Bg = g_wdt_h + (size_t)n0 * HH;

    auto load_chunk = [&](int c) {
        const int k0 = c << 6;
        const uint32_t base = sb + (c & 1) * 32768;
#pragma unroll
        for (int q = 0; q < 4; q++) {
            int u = q * 256 + tid;
            int row = u >> 3, un = u & 7;
            uint32_t off = SWZ(row * 128 + un * 16);
            cpa16(base + off,         Ag + (size_t)row * HH + k0 + un * 8);
            cpa16(base + 16384 + off, Bg + (size_t)row * HH + k0 + un * 8);
        }
        asm volatile("cp.async.commit_group;" ::: "memory");
    };

    float acc[2][8][4];
#pragma unroll
    for (int mi = 0; mi < 2; mi++)
#pragma unroll
        for (int ni = 0; ni < 8; ni++)
#pragma unroll
            for (int k = 0; k < 4; k++) acc[mi][ni][k] = 0.0f;

    load_chunk(0);
    load_chunk(1);

    for (int c = 0; c < 16; c++) {
        if (c < 15) asm volatile("cp.async.wait_group 1;" ::: "memory");
        else        asm volatile("cp.async.wait_group 0;" ::: "memory");
        __syncthreads();

        const uint32_t base = sb + (c & 1) * 32768;
#pragma unroll
        for (int kss = 0; kss < 4; kss++) {
            uint32_t a[2][4];
#pragma unroll
            for (int mi = 0; mi < 2; mi++) {
                int row = wr * 32 + mi * 16 + (l & 15);
                int un  = kss * 2 + (l >> 4);
                uint32_t addr = base + SWZ(row * 128 + un * 16);
                asm volatile("ldmatrix.sync.aligned.m8n8.x4.shared.b16 {%0,%1,%2,%3}, [%4];"
                             : "=r"(a[mi][0]), "=r"(a[mi][1]), "=r"(a[mi][2]), "=r"(a[mi][3])
                             : "r"(addr));
            }
            uint32_t bf[4][4];
#pragma unroll
            for (int nb = 0; nb < 4; nb++) {
                int row = wc * 64 + nb * 16 + ((l >> 4) << 3) + (l & 7);
                int un  = kss * 2 + ((l >> 3) & 1);
                uint32_t addr = base + 16384 + SWZ(row * 128 + un * 16);
                asm volatile("ldmatrix.sync.aligned.m8n8.x4.shared.b16 {%0,%1,%2,%3}, [%4];"
                             : "=r"(bf[nb][0]), "=r"(bf[nb][1]), "=r"(bf[nb][2]), "=r"(bf[nb][3])
                             : "r"(addr));
            }
#pragma unroll
            for (int mi = 0; mi < 2; mi++)
#pragma unroll
                for (int ni = 0; ni < 8; ni++) {
                    uint32_t b0 = bf[ni >> 1][(ni & 1) * 2 + 0];
                    uint32_t b1 = bf[ni >> 1][(ni & 1) * 2 + 1];
                    asm volatile(
                        "mma.sync.aligned.m16n8k16.row.col.f32.f16.f16.f32 "
                        "{%0,%1,%2,%3}, {%4,%5,%6,%7}, {%8,%9}, {%0,%1,%2,%3};"
                        : "+f"(acc[mi][ni][0]), "+f"(acc[mi][ni][1]),
                          "+f"(acc[mi][ni][2]), "+f"(acc[mi][ni][3])
                        : "r"(a[mi][0]), "r"(a[mi][1]), "r"(a[mi][2]), "r"(a[mi][3]),
                          "r"(b0), "r"(b1));
                }
        }
        __syncthreads();
        if (c + 2 < 16) load_chunk(c + 2);
    }

    // Epilogue: BN scale/shift, write fp32
#pragma unroll
    for (int mi = 0; mi < 2; mi++) {
        int r0 = m0 + wr * 32 + mi * 16 + (l >> 2);
#pragma unroll
        for (int ni = 0; ni < 8; ni++) {
            int cl = wc * 64 + ni * 8 + (l & 3) * 2;
            float s0 = sc[cl], s1 = sc[cl + 1];
            float f0 = sf[cl], f1 = sf[cl + 1];
            float2 v0 = make_float2(acc[mi][ni][0] * s0 + f0,
                                    acc[mi][ni][1] * s1 + f1);
            float2 v1 = make_float2(acc[mi][ni][2] * s0 + f0,
                                    acc[mi][ni][3] * s1 + f1);
            *(float2*)(out + (size_t)r0 * VV + n0 + cl) = v0;
            *(float2*)(out + (size_t)(r0 + 8) * VV + n0 + cl) = v1;
        }
    }
}

// ---------------------------------------------------------------------------
extern "C" void kernel_launch(void* const* d_in, const int* in_sizes, int n_in,
                              void* d_out, int out_size)
{
    const int*   X     = (const int*)  d_in[0];
    const float* h0    = (const float*)d_in[1];
    const float* c0    = (const float*)d_in[2];
    const float* emb   = (const float*)d_in[3];
    const float* W     = (const float*)d_in[4];
    const float* U     = (const float*)d_in[5];
    const float* b     = (const float*)d_in[6];
    const float* Wd    = (const float*)d_in[7];
    const float* bd    = (const float*)d_in[8];
    const float* gamma = (const float*)d_in[9];
    const float* beta  = (const float*)d_in[10];
    const float* mmean = (const float*)d_in[11];
    const float* mvar  = (const float*)d_in[12];
    float* out = (float*)d_out;

    cudaFuncSetAttribute(lstm_persistent_kernel,
                         cudaFuncAttributeMaxDynamicSharedMemorySize, 168192);
    cudaFuncSetAttribute(proj_mma_kernel,
                         cudaFuncAttributeMaxDynamicSharedMemorySize, 66560);

    init_bar_kernel<<<1, 1>>>();

    // Wd transpose + fp16 convert (independent)
    wd_split_kernel<<<dim3(VV / 32, HH / 32), 256>>>(Wd);

    // Xz = emb[X]@W + b (fp32)
    gemm_xz_kernel<<<dim3(GG / 128, MM / 128), 256>>>(X, emb, W, b);

    // persistent LSTM over all 128 steps
    lstm_persistent_kernel<<<128, 128, 168192>>>(h0, c0, U);

    // tensor-core projection + BN
    proj_mma_kernel<<<dim3(VV / 128, MM / 128), 256, 66560>>>(
        bd, gamma, beta, mmean, mvar, out);
}

// round 11
// speedup vs baseline: 1.8831x; 1.8831x over previous
#include <cuda_runtime.h>
#include <cuda_fp16.h>
#include <math.h>
#include <stdint.h>

// Shapes (fixed): B=32, T=128, V=32000, E=512, H=1024, 4H=4096
#define BB 32
#define TT 128
#define VV 32000
#define EE 512
#define HH 1024
#define GG 4096
#define MM 4096   // T*B rows

// ------------------------- static device scratch ---------------------------
__device__ float  g_xz[(size_t)MM * GG];        // emb[X]@W + b  (64 MB)
__device__ float  g_h[2][BB * HH];              // h ping-pong
__device__ __half g_hs_h[(size_t)MM * HH];      // hs fp16 (8 MB) — proj A
__device__ __half g_wdt_h[(size_t)VV * HH];     // Wd^T fp16 [V][K] (64 MB)
__device__ __half g_a16[(size_t)MM * EE];       // gathered emb fp16 (4 MB)
__device__ __half g_wt16[(size_t)GG * EE];      // W^T fp16 [4H][E] (4 MB)
__device__ unsigned g_bar;                      // persistent-kernel barrier

__device__ __forceinline__ float sigm(float x) { return 1.0f / (1.0f + expf(-x)); }

__device__ __forceinline__ uint32_t smem_u32(const void* p) {
    uint32_t a;
    asm("{ .reg .u64 t; cvta.to.shared.u64 t, %1; cvt.u32.u64 %0, t; }"
        : "=r"(a) : "l"(p));
    return a;
}
__device__ __forceinline__ void cpa16(uint32_t d, const void* s) {
    asm volatile("cp.async.cg.shared.global [%0], [%1], 16;" :: "r"(d), "l"(s));
}
#define SWZ(x) ((x) ^ (((x) >> 3) & 0x70))

// ---------------------------------------------------------------------------
__global__ void init_bar_kernel() { g_bar = 0u; }

// ---------------------------------------------------------------------------
// Prep A: gather emb rows -> fp16, row r = t*32+b
// ---------------------------------------------------------------------------
__global__ void __launch_bounds__(128) gather_conv_kernel(
    const int* __restrict__ X, const float* __restrict__ emb)
{
    const int r = blockIdx.x;
    const int t = r >> 5, b = r & 31;
    const int e = X[b * TT + t];
    float4 v = ((const float4*)(emb + (size_t)e * EE))[threadIdx.x];
    __half2 h01 = __floats2half2_rn(v.x, v.y);
    __half2 h23 = __floats2half2_rn(v.z, v.w);
    uint2 pk;
    pk.x = *(uint32_t*)&h01;
    pk.y = *(uint32_t*)&h23;
    *(uint2*)(g_a16 + (size_t)r * EE + threadIdx.x * 4) = pk;
}

// ---------------------------------------------------------------------------
// Prep B: W [E=512][4H=4096] -> W^T fp16 [4H][E]
// ---------------------------------------------------------------------------
__global__ void __launch_bounds__(256) wt_conv_kernel(const float* __restrict__ W)
{
    __shared__ float tb[32][33];
    const int n0 = blockIdx.x * 32;
    const int k0 = blockIdx.y * 32;
    const int tx = threadIdx.x & 31;
    const int ty0 = threadIdx.x >> 5;
#pragma unroll
    for (int ty = ty0; ty < 32; ty += 8)
        tb[ty][tx] = W[(size_t)(k0 + ty) * GG + n0 + tx];
    __syncthreads();
#pragma unroll
    for (int ty = ty0; ty < 32; ty += 8)
        g_wt16[(size_t)(n0 + ty) * EE + k0 + tx] = __float2half(tb[tx][ty]);
}

// ---------------------------------------------------------------------------
// Prep C: Wd [K=1024][V] -> Wd^T fp16 [V][K]
// ---------------------------------------------------------------------------
__global__ void __launch_bounds__(256) wd_split_kernel(const float* __restrict__ Wd)
{
    __shared__ float tb[32][33];
    const int v0 = blockIdx.x * 32;
    const int k0 = blockIdx.y * 32;
    const int tx = threadIdx.x & 31;
    const int ty0 = threadIdx.x >> 5;
#pragma unroll
    for (int ty = ty0; ty < 32; ty += 8)
        tb[ty][tx] = Wd[(size_t)(k0 + ty) * VV + v0 + tx];
    __syncthreads();
#pragma unroll
    for (int ty = ty0; ty < 32; ty += 8)
        g_wdt_h[(size_t)(v0 + ty) * HH + k0 + tx] = __float2half(tb[tx][ty]);
}

// ---------------------------------------------------------------------------
// Templated HMMA GEMM + epilogue:  out = epi( A @ B^T )
//   Operands are device globals, selected IN DEVICE CODE by BN (host code
//   must never take the address of a __device__ symbol):
//     BN=false: A=g_a16 [M][512],  B=g_wt16 [4096][512],  out=g_xz (+bias)
//     BN=true : A=g_hs_h [M][1024],B=g_wdt_h [V][1024],   out=outp (BN epi)
//   CTA tile 128x128, 8 warps (32m x 64n), K-chunks of 64, cp.async x2.
// ---------------------------------------------------------------------------
template <int KD, bool BN>
__global__ void __launch_bounds__(256, 1) mma_epi_kernel(
    const float* __restrict__ bias, const float* __restrict__ gamma,
    const float* __restrict__ beta, const float* __restrict__ mmean,
    const float* __restrict__ mvar, float* __restrict__ outp, int ldo)
{
    extern __shared__ char smem[];
    const int tid = threadIdx.x;
    const int wid = tid >> 5, l = tid & 31;
    const int wr = wid & 3, wc = wid >> 2;
    const int m0 = blockIdx.y << 7;
    const int n0 = blockIdx.x << 7;
    constexpr int CH = KD / 64;

    // device-side operand selection (fixes host-shadow pointer bug)
    const __half* Ag0 = BN ? g_hs_h : g_a16;
    const __half* Bg0 = BN ? g_wdt_h : g_wt16;
    float* op = BN ? outp : g_xz;

    float* sc = (float*)(smem + 65536);
    float* sf = (float*)(smem + 66048);
    if (tid < 128) {
        int n = n0 + tid;
        float scv = 1.0f, sfv = bias[n];
        if (BN) {
            float iv = gamma[n] * rsqrtf(mvar[n] + 1e-3f);
            scv = iv;
            sfv = beta[n] + (bias[n] - mmean[n]) * iv;
        }
        sc[tid] = scv;
        sf[tid] = sfv;
    }

    const uint32_t sb = smem_u32(smem);
    const __half* Ag = Ag0 + (size_t)m0 * KD;
    const __half* Bg = Bg0 + (size_t)n0 * KD;

    auto load_chunk = [&](int c) {
        const int k0 = c << 6;
        const uint32_t base = sb + (c & 1) * 32768;
#pragma unroll
        for (int q = 0; q < 4; q++) {
            int u = q * 256 + tid;
            int row = u >> 3, un = u & 7;
            uint32_t off = SWZ(row * 128 + un * 16);
            cpa16(base + off,         Ag + (size_t)row * KD + k0 + un * 8);
            cpa16(base + 16384 + off, Bg + (size_t)row * KD + k0 + un * 8);
        }
        asm volatile("cp.async.commit_group;" ::: "memory");
    };

    float acc[2][8][4];
#pragma unroll
    for (int mi = 0; mi < 2; mi++)
#pragma unroll
        for (int ni = 0; ni < 8; ni++)
#pragma unroll
            for (int k = 0; k < 4; k++) acc[mi][ni][k] = 0.0f;

    load_chunk(0);
    load_chunk(1);

    for (int c = 0; c < CH; c++) {
        if (c < CH - 1) asm volatile("cp.async.wait_group 1;" ::: "memory");
        else            asm volatile("cp.async.wait_group 0;" ::: "memory");
        __syncthreads();

        const uint32_t base = sb + (c & 1) * 32768;
#pragma unroll
        for (int kss = 0; kss < 4; kss++) {
            uint32_t a[2][4];
#pragma unroll
            for (int mi = 0; mi < 2; mi++) {
                int row = wr * 32 + mi * 16 + (l & 15);
                int un  = kss * 2 + (l >> 4);
                uint32_t addr = base + SWZ(row * 128 + un * 16);
                asm volatile("ldmatrix.sync.aligned.m8n8.x4.shared.b16 {%0,%1,%2,%3}, [%4];"
                             : "=r"(a[mi][0]), "=r"(a[mi][1]), "=r"(a[mi][2]), "=r"(a[mi][3])
                             : "r"(addr));
            }
            uint32_t bf[4][4];
#pragma unroll
            for (int nb = 0; nb < 4; nb++) {
                int row = wc * 64 + nb * 16 + ((l >> 4) << 3) + (l & 7);
                int un  = kss * 2 + ((l >> 3) & 1);
                uint32_t addr = base + 16384 + SWZ(row * 128 + un * 16);
                asm volatile("ldmatrix.sync.aligned.m8n8.x4.shared.b16 {%0,%1,%2,%3}, [%4];"
                             : "=r"(bf[nb][0]), "=r"(bf[nb][1]), "=r"(bf[nb][2]), "=r"(bf[nb][3])
                             : "r"(addr));
            }
#pragma unroll
            for (int mi = 0; mi < 2; mi++)
#pragma unroll
                for (int ni = 0; ni < 8; ni++) {
                    uint32_t b0 = bf[ni >> 1][(ni & 1) * 2 + 0];
                    uint32_t b1 = bf[ni >> 1][(ni & 1) * 2 + 1];
                    asm volatile(
                        "mma.sync.aligned.m16n8k16.row.col.f32.f16.f16.f32 "
                        "{%0,%1,%2,%3}, {%4,%5,%6,%7}, {%8,%9}, {%0,%1,%2,%3};"
                        : "+f"(acc[mi][ni][0]), "+f"(acc[mi][ni][1]),
                          "+f"(acc[mi][ni][2]), "+f"(acc[mi][ni][3])
                        : "r"(a[mi][0]), "r"(a[mi][1]), "r"(a[mi][2]), "r"(a[mi][3]),
                          "r"(b0), "r"(b1));
                }
        }
        __syncthreads();
        if (c + 2 < CH) load_chunk(c + 2);
    }

#pragma unroll
    for (int mi = 0; mi < 2; mi++) {
        int r0 = m0 + wr * 32 + mi * 16 + (l >> 2);
#pragma unroll
        for (int ni = 0; ni < 8; ni++) {
            int cl = wc * 64 + ni * 8 + (l & 3) * 2;
            float s0 = sc[cl], s1 = sc[cl + 1];
            float f0 = sf[cl], f1 = sf[cl + 1];
            float2 v0 = make_float2(acc[mi][ni][0] * s0 + f0,
                                    acc[mi][ni][1] * s1 + f1);
            float2 v1 = make_float2(acc[mi][ni][2] * s0 + f0,
                                    acc[mi][ni][3] * s1 + f1);
            *(float2*)(op + (size_t)r0 * ldo + n0 + cl) = v0;
            *(float2*)(op + (size_t)(r0 + 8) * ldo + n0 + cl) = v1;
        }
    }
}

// ---------------------------------------------------------------------------
// Persistent LSTM v2: 128 CTAs (1/SM), 256 threads (8 warps), 4-way K-split.
//   CTA owns j-octet jbase..jbase+7 (x 4 gates).  U staged once (128 KB,
//   gate-interleaved).  Per step: h staged in 2 chunks of [32][512] (fp32,
//   __ldcg), each ks-quarter accumulates its 128-k window, smem reduce,
//   group 0 does gate math (c in registers), h via stcg, hs as fp16.
// Dyn smem: su 131072 + sh 32*520*4 = 66560 + red 12288 = 209920 B.
// ---------------------------------------------------------------------------
#define SH_PITCH 520
__global__ void __launch_bounds__(256, 1) lstm_persistent_kernel(
    const float* __restrict__ h0, const float* __restrict__ c0,
    const float* __restrict__ U)
{
    extern __shared__ float dsm[];
    float* su  = dsm;                        // [1024][32]
    float* sh  = dsm + 1024 * 32;            // [32][520]
    float* red = sh + 32 * SH_PITCH;         // [3][64][16]

    const int tid = threadIdx.x;
    const int ks  = tid >> 6;                // 0..3
    const int pos = tid & 63;
    const int bg  = pos >> 3;                // 0..7
    const int jl  = pos & 7;                 // 0..7
    const int jbase = blockIdx.x * 8;

    // stage U once: su[k][c], c = jl*4+g  <-  U[k][g*1024 + jbase + jl]
    for (int i = tid; i < 1024 * 32; i += 256) {
        int k = i >> 5, c = i & 31;
        int g = c & 3, j2 = c >> 2;
        su[k * 32 + c] = U[(size_t)k * GG + g * 1024 + jbase + j2];
    }

    float creg[4];
    if (ks == 0) {
#pragma unroll
        for (int bi = 0; bi < 4; bi++)
            creg[bi] = c0[(bg * 4 + bi) * HH + jbase + jl];
    }
    __syncthreads();

    for (int t = 0; t < TT; t++) {
        const float* hprev = (t == 0) ? h0 : g_h[(t - 1) & 1];

        float acc[4][4];
#pragma unroll
        for (int bi = 0; bi < 4; bi++)
#pragma unroll
            for (int g = 0; g < 4; g++) acc[bi][g] = 0.0f;

#pragma unroll
        for (int cc = 0; cc < 2; cc++) {
            __syncthreads();
            // stage sh[b][0..511] = hprev[b][cc*512 ..], float4, L2-coherent
            for (int i = tid; i < (32 * 512) / 4; i += 256) {
                int e4 = i * 4;
                int b = e4 >> 9, kk = e4 & 511;
                float4 v = __ldcg((const float4*)&hprev[b * HH + cc * 512 + kk]);
                *(float4*)&sh[b * SH_PITCH + kk] = v;
            }
            __syncthreads();

            const float* suk = su + (size_t)(cc * 512 + ks * 128) * 32 + (jl << 2);
            const float* shb = sh + (bg * 4) * SH_PITCH + ks * 128;
#pragma unroll 4
            for (int kk = 0; kk < 128; kk++) {
                const float4 ug = *(const float4*)(suk + kk * 32);
                float hv0 = shb[0 * SH_PITCH + kk];
                float hv1 = shb[1 * SH_PITCH + kk];
                float hv2 = shb[2 * SH_PITCH + kk];
                float hv3 = shb[3 * SH_PITCH + kk];
                acc[0][0] = fmaf(hv0, ug.x, acc[0][0]);
                acc[0][1] = fmaf(hv0, ug.y, acc[0][1]);
                acc[0][2] = fmaf(hv0, ug.z, acc[0][2]);
                acc[0][3] = fmaf(hv0, ug.w, acc[0][3]);
                acc[1][0] = fmaf(hv1, ug.x, acc[1][0]);
                acc[1][1] = fmaf(hv1, ug.y, acc[1][1]);
                acc[1][2] = fmaf(hv1, ug.z, acc[1][2]);
                acc[1][3] = fmaf(hv1, ug.w, acc[1][3]);
                acc[2][0] = fmaf(hv2, ug.x, acc[2][0]);
                acc[2][1] = fmaf(hv2, ug.y, acc[2][1]);
                acc[2][2] = fmaf(hv2, ug.z, acc[2][2]);
                acc[2][3] = fmaf(hv2, ug.w, acc[2][3]);
                acc[3][0] = fmaf(hv3, ug.x, acc[3][0]);
                acc[3][1] = fmaf(hv3, ug.y, acc[3][1]);
                acc[3][2] = fmaf(hv3, ug.z, acc[3][2]);
                acc[3][3] = fmaf(hv3, ug.w, acc[3][3]);
            }
        }

        if (ks != 0) {
            float* rp = red + (ks - 1) * 1024 + pos * 16;
#pragma unroll
            for (int bi = 0; bi < 4; bi++)
#pragma unroll
                for (int g = 0; g < 4; g++) rp[bi * 4 + g] = acc[bi][g];
        }
        __syncthreads();

        if (ks == 0) {
            const float* xzr = g_xz + (size_t)t * BB * GG;
            float* hnext = g_h[t & 1];
            const int j = jbase + jl;
            const float* rp = red + pos * 16;
#pragma unroll
            for (int bi = 0; bi < 4; bi++) {
                int b = bg * 4 + bi;
                const float* xb = xzr + (size_t)b * GG;
                float zi = acc[bi][0] + rp[bi*4+0] + rp[1024 + bi*4+0] + rp[2048 + bi*4+0] + xb[j];
                float zf = acc[bi][1] + rp[bi*4+1] + rp[1024 + bi*4+1] + rp[2048 + bi*4+1] + xb[HH + j];
                float zg = acc[bi][2] + rp[bi*4+2] + rp[1024 + bi*4+2] + rp[2048 + bi*4+2] + xb[2*HH + j];
                float zo = acc[bi][3] + rp[bi*4+3] + rp[1024 + bi*4+3] + rp[2048 + bi*4+3] + xb[3*HH + j];
                float cn = sigm(zf) * creg[bi] + sigm(zi) * tanhf(zg);
                float hn = sigm(zo) * tanhf(cn);
                creg[bi] = cn;
                __stcg(&hnext[b * HH + j], hn);
                g_hs_h[(size_t)(t * BB + b) * HH + j] = __float2half(hn);
            }
        }

        __threadfence();
        __syncthreads();
        if (tid == 0) {
            atomicAdd(&g_bar, 1u);
            unsigned target = 128u * (unsigned)(t + 1);
            while (atomicAdd(&g_bar, 0u) < target) { }
        }
        __syncthreads();
    }
}

// ---------------------------------------------------------------------------
extern "C" void kernel_launch(void* const* d_in, const int* in_sizes, int n_in,
                              void* d_out, int out_size)
{
    const int*   X     = (const int*)  d_in[0];
    const float* h0    = (const float*)d_in[1];
    const float* c0    = (const float*)d_in[2];
    const float* emb   = (const float*)d_in[3];
    const float* W     = (const float*)d_in[4];
    const float* U     = (const float*)d_in[5];
    const float* b     = (const float*)d_in[6];
    const float* Wd    = (const float*)d_in[7];
    const float* bd    = (const float*)d_in[8];
    const float* gamma = (const float*)d_in[9];
    const float* beta  = (const float*)d_in[10];
    const float* mmean = (const float*)d_in[11];
    const float* mvar  = (const float*)d_in[12];
    float* out = (float*)d_out;

    cudaFuncSetAttribute(lstm_persistent_kernel,
                         cudaFuncAttributeMaxDynamicSharedMemorySize, 209920);
    cudaFuncSetAttribute(mma_epi_kernel<512, false>,
                         cudaFuncAttributeMaxDynamicSharedMemorySize, 66560);
    cudaFuncSetAttribute(mma_epi_kernel<1024, true>,
                         cudaFuncAttributeMaxDynamicSharedMemorySize, 66560);

    init_bar_kernel<<<1, 1>>>();

    // preps
    gather_conv_kernel<<<MM, 128>>>(X, emb);
    wt_conv_kernel<<<dim3(GG / 32, EE / 32), 256>>>(W);
    wd_split_kernel<<<dim3(VV / 32, HH / 32), 256>>>(Wd);

    // Xz = emb[X]@W + b  (HMMA fp16; writes g_xz internally)
    mma_epi_kernel<512, false><<<dim3(GG / 128, MM / 128), 256, 66560>>>(
        b, nullptr, nullptr, nullptr, nullptr, nullptr, GG);

    // persistent LSTM over all 128 steps
    lstm_persistent_kernel<<<128, 256, 209920>>>(h0, c0, U);

    // projection + BN (HMMA fp16)
    mma_epi_kernel<1024, true><<<dim3(VV / 128, MM / 128), 256, 66560>>>(
        bd, gamma, beta, mmean, mvar, out, VV);
}

// round 12
// speedup vs baseline: 3.8772x; 2.0590x over previous
#include <cuda_runtime.h>
#include <cuda_fp16.h>
#include <math.h>
#include <stdint.h>

// Shapes (fixed): B=32, T=128, V=32000, E=512, H=1024, 4H=4096
#define BB 32
#define TT 128
#define VV 32000
#define EE 512
#define HH 1024
#define GG 4096
#define MM 4096   // T*B rows

// ------------------------- static device scratch ---------------------------
__device__ float  g_xz[(size_t)MM * GG];        // emb[X]@W + b  (64 MB)
__device__ __half g_hs_h[(size_t)MM * HH];      // hs fp16 archive (8 MB) — also h state
__device__ __half g_h016[BB * HH];              // h0 fp16
__device__ __half g_wdt_h[(size_t)VV * HH];     // Wd^T fp16 [V][K] (64 MB)
__device__ __half g_a16[(size_t)MM * EE];       // gathered emb fp16 (4 MB)
__device__ __half g_wt16[(size_t)GG * EE];      // W^T fp16 [4H][E] (4 MB)
__device__ __half g_ut16[(size_t)GG * HH];      // U^T fp16 [4H][H] (8 MB)
__device__ unsigned g_bar;                      // persistent-kernel barrier

__device__ __forceinline__ float sigm(float x) { return 1.0f / (1.0f + expf(-x)); }

__device__ __forceinline__ uint32_t smem_u32(const void* p) {
    uint32_t a;
    asm("{ .reg .u64 t; cvta.to.shared.u64 t, %1; cvt.u32.u64 %0, t; }"
        : "=r"(a) : "l"(p));
    return a;
}
__device__ __forceinline__ void cpa16(uint32_t d, const void* s) {
    asm volatile("cp.async.cg.shared.global [%0], [%1], 16;" :: "r"(d), "l"(s));
}
#define SWZ(x) ((x) ^ (((x) >> 3) & 0x70))

// ---------------------------------------------------------------------------
__global__ void init_bar_kernel() { g_bar = 0u; }

// ---------------------------------------------------------------------------
// Prep A: gather emb rows -> fp16, row r = t*32+b
// ---------------------------------------------------------------------------
__global__ void __launch_bounds__(128) gather_conv_kernel(
    const int* __restrict__ X, const float* __restrict__ emb)
{
    const int r = blockIdx.x;
    const int t = r >> 5, b = r & 31;
    const int e = X[b * TT + t];
    float4 v = ((const float4*)(emb + (size_t)e * EE))[threadIdx.x];
    __half2 h01 = __floats2half2_rn(v.x, v.y);
    __half2 h23 = __floats2half2_rn(v.z, v.w);
    uint2 pk;
    pk.x = *(uint32_t*)&h01;
    pk.y = *(uint32_t*)&h23;
    *(uint2*)(g_a16 + (size_t)r * EE + threadIdx.x * 4) = pk;
}

// ---------------------------------------------------------------------------
// Prep B: W [E=512][4H] -> W^T fp16 [4H][E]
// ---------------------------------------------------------------------------
__global__ void __launch_bounds__(256) wt_conv_kernel(const float* __restrict__ W)
{
    __shared__ float tb[32][33];
    const int n0 = blockIdx.x * 32;
    const int k0 = blockIdx.y * 32;
    const int tx = threadIdx.x & 31;
    const int ty0 = threadIdx.x >> 5;
#pragma unroll
    for (int ty = ty0; ty < 32; ty += 8)
        tb[ty][tx] = W[(size_t)(k0 + ty) * GG + n0 + tx];
    __syncthreads();
#pragma unroll
    for (int ty = ty0; ty < 32; ty += 8)
        g_wt16[(size_t)(n0 + ty) * EE + k0 + tx] = __float2half(tb[tx][ty]);
}

// ---------------------------------------------------------------------------
// Prep B2: U [H=1024][4H] -> U^T fp16 [4H][H]
// ---------------------------------------------------------------------------
__global__ void __launch_bounds__(256) ut_conv_kernel(const float* __restrict__ U)
{
    __shared__ float tb[32][33];
    const int n0 = blockIdx.x * 32;
    const int k0 = blockIdx.y * 32;
    const int tx = threadIdx.x & 31;
    const int ty0 = threadIdx.x >> 5;
#pragma unroll
    for (int ty = ty0; ty < 32; ty += 8)
        tb[ty][tx] = U[(size_t)(k0 + ty) * GG + n0 + tx];
    __syncthreads();
#pragma unroll
    for (int ty = ty0; ty < 32; ty += 8)
        g_ut16[(size_t)(n0 + ty) * HH + k0 + tx] = __float2half(tb[tx][ty]);
}

// ---------------------------------------------------------------------------
// Prep C: Wd [K=1024][V] -> Wd^T fp16 [V][K]
// ---------------------------------------------------------------------------
__global__ void __launch_bounds__(256) wd_split_kernel(const float* __restrict__ Wd)
{
    __shared__ float tb[32][33];
    const int v0 = blockIdx.x * 32;
    const int k0 = blockIdx.y * 32;
    const int tx = threadIdx.x & 31;
    const int ty0 = threadIdx.x >> 5;
#pragma unroll
    for (int ty = ty0; ty < 32; ty += 8)
        tb[ty][tx] = Wd[(size_t)(k0 + ty) * VV + v0 + tx];
    __syncthreads();
#pragma unroll
    for (int ty = ty0; ty < 32; ty += 8)
        g_wdt_h[(size_t)(v0 + ty) * HH + k0 + tx] = __float2half(tb[tx][ty]);
}

// ---------------------------------------------------------------------------
// Prep D: h0 fp32 -> fp16
// ---------------------------------------------------------------------------
__global__ void __launch_bounds__(256) h0_conv_kernel(const float* __restrict__ h0)
{
    int i = blockIdx.x * 256 + threadIdx.x;
    g_h016[i] = __float2half(h0[i]);
}

// ---------------------------------------------------------------------------
// Templated HMMA GEMM + epilogue (unchanged from R11):
//   BN=false: A=g_a16 [M][512],  B=g_wt16 [4096][512],  out=g_xz (+bias)
//   BN=true : A=g_hs_h [M][1024],B=g_wdt_h [V][1024],   out=outp (BN epi)
// ---------------------------------------------------------------------------
template <int KD, bool BN>
__global__ void __launch_bounds__(256, 1) mma_epi_kernel(
    const float* __restrict__ bias, const float* __restrict__ gamma,
    const float* __restrict__ beta, const float* __restrict__ mmean,
    const float* __restrict__ mvar, float* __restrict__ outp, int ldo)
{
    extern __shared__ char smem[];
    const int tid = threadIdx.x;
    const int wid = tid >> 5, l = tid & 31;
    const int wr = wid & 3, wc = wid >> 2;
    const int m0 = blockIdx.y << 7;
    const int n0 = blockIdx.x << 7;
    constexpr int CH = KD / 64;

    const __half* Ag0 = BN ? g_hs_h : g_a16;
    const __half* Bg0 = BN ? g_wdt_h : g_wt16;
    float* op = BN ? outp : g_xz;

    float* sc = (float*)(smem + 65536);
    float* sf = (float*)(smem + 66048);
    if (tid < 128) {
        int n = n0 + tid;
        float scv = 1.0f, sfv = bias[n];
        if (BN) {
            float iv = gamma[n] * rsqrtf(mvar[n] + 1e-3f);
            scv = iv;
            sfv = beta[n] + (bias[n] - mmean[n]) * iv;
        }
        sc[tid] = scv;
        sf[tid] = sfv;
    }

    const uint32_t sb = smem_u32(smem);
    const __half* Ag = Ag0 + (size_t)m0 * KD;
    const __half* Bg = Bg0 + (size_t)n0 * KD;

    auto load_chunk = [&](int c) {
        const int k0 = c << 6;
        const uint32_t base = sb + (c & 1) * 32768;
#pragma unroll
        for (int q = 0; q < 4; q++) {
            int u = q * 256 + tid;
            int row = u >> 3, un = u & 7;
            uint32_t off = SWZ(row * 128 + un * 16);
            cpa16(base + off,         Ag + (size_t)row * KD + k0 + un * 8);
            cpa16(base + 16384 + off, Bg + (size_t)row * KD + k0 + un * 8);
        }
        asm volatile("cp.async.commit_group;" ::: "memory");
    };

    float acc[2][8][4];
#pragma unroll
    for (int mi = 0; mi < 2; mi++)
#pragma unroll
        for (int ni = 0; ni < 8; ni++)
#pragma unroll
            for (int k = 0; k < 4; k++) acc[mi][ni][k] = 0.0f;

    load_chunk(0);
    load_chunk(1);

    for (int c = 0; c < CH; c++) {
        if (c < CH - 1) asm volatile("cp.async.wait_group 1;" ::: "memory");
        else            asm volatile("cp.async.wait_group 0;" ::: "memory");
        __syncthreads();

        const uint32_t base = sb + (c & 1) * 32768;
#pragma unroll
        for (int kss = 0; kss < 4; kss++) {
            uint32_t a[2][4];
#pragma unroll
            for (int mi = 0; mi < 2; mi++) {
                int row = wr * 32 + mi * 16 + (l & 15);
                int un  = kss * 2 + (l >> 4);
                uint32_t addr = base + SWZ(row * 128 + un * 16);
                asm volatile("ldmatrix.sync.aligned.m8n8.x4.shared.b16 {%0,%1,%2,%3}, [%4];"
                             : "=r"(a[mi][0]), "=r"(a[mi][1]), "=r"(a[mi][2]), "=r"(a[mi][3])
                             : "r"(addr));
            }
            uint32_t bf[4][4];
#pragma unroll
            for (int nb = 0; nb < 4; nb++) {
                int row = wc * 64 + nb * 16 + ((l >> 4) << 3) + (l & 7);
                int un  = kss * 2 + ((l >> 3) & 1);
                uint32_t addr = base + 16384 + SWZ(row * 128 + un * 16);
                asm volatile("ldmatrix.sync.aligned.m8n8.x4.shared.b16 {%0,%1,%2,%3}, [%4];"
                             : "=r"(bf[nb][0]), "=r"(bf[nb][1]), "=r"(bf[nb][2]), "=r"(bf[nb][3])
                             : "r"(addr));
            }
#pragma unroll
            for (int mi = 0; mi < 2; mi++)
#pragma unroll
                for (int ni = 0; ni < 8; ni++) {
                    uint32_t b0 = bf[ni >> 1][(ni & 1) * 2 + 0];
                    uint32_t b1 = bf[ni >> 1][(ni & 1) * 2 + 1];
                    asm volatile(
                        "mma.sync.aligned.m16n8k16.row.col.f32.f16.f16.f32 "
                        "{%0,%1,%2,%3}, {%4,%5,%6,%7}, {%8,%9}, {%0,%1,%2,%3};"
                        : "+f"(acc[mi][ni][0]), "+f"(acc[mi][ni][1]),
                          "+f"(acc[mi][ni][2]), "+f"(acc[mi][ni][3])
                        : "r"(a[mi][0]), "r"(a[mi][1]), "r"(a[mi][2]), "r"(a[mi][3]),
                          "r"(b0), "r"(b1));
                }
        }
        __syncthreads();
        if (c + 2 < CH) load_chunk(c + 2);
    }

#pragma unroll
    for (int mi = 0; mi < 2; mi++) {
        int r0 = m0 + wr * 32 + mi * 16 + (l >> 2);
#pragma unroll
        for (int ni = 0; ni < 8; ni++) {
            int cl = wc * 64 + ni * 8 + (l & 3) * 2;
            float s0 = sc[cl], s1 = sc[cl + 1];
            float f0 = sf[cl], f1 = sf[cl + 1];
            float2 v0 = make_float2(acc[mi][ni][0] * s0 + f0,
                                    acc[mi][ni][1] * s1 + f1);
            float2 v1 = make_float2(acc[mi][ni][2] * s0 + f0,
                                    acc[mi][ni][3] * s1 + f1);
            *(float2*)(op + (size_t)r0 * ldo + n0 + cl) = v0;
            *(float2*)(op + (size_t)(r0 + 8) * ldo + n0 + cl) = v1;
        }
    }
}

// ---------------------------------------------------------------------------
// Persistent LSTM v3 (HMMA): 128 CTAs (1/SM), 256 threads (8 warps).
//   CTA owns 32 output cols: local n -> global col (n&3)*1024 + jbase + (n>>2).
//   U^T slice staged ONCE as fp16 in 64 KB swizzled smem (16 chunks x [32][128B]).
//   Per step: A = h(t-1) fp16 from g_hs_h archive (cp.async, 64 KB, same layout),
//   warp w computes k-chunks {2w, 2w+1} via mma.m16n8k16 (32x32 tile, K=128),
//   partials -> padded smem, 256 threads do gate math (c in register, xz fp32),
//   hn written fp16 straight into the archive; global atomic barrier per step.
// Dyn smem: U 65536 + A 65536 + zred 8*32*36*4 = 36864  -> 167936 B.
// ---------------------------------------------------------------------------
__global__ void __launch_bounds__(256, 1) lstm_mma_kernel(const float* __restrict__ c0)
{
    extern __shared__ char sm[];
    const uint32_t sb = smem_u32(sm);
    float* zred = (float*)(sm + 131072);     // [8][32][36] fp32, padded

    const int tid = threadIdx.x;
    const int wid = tid >> 5, l = tid & 31;
    const int jbase = blockIdx.x * 8;

    // ---- stage U^T slice once: local row n -> global row (n&3)*1024+jbase+(n>>2)
#pragma unroll
    for (int it = 0; it < 16; it++) {
        int u = it * 256 + tid;              // 0..4095
        int chunk = u >> 8;
        int rem = u & 255;
        int row = rem >> 3, seg = rem & 7;
        int gr = (row & 3) * 1024 + jbase + (row >> 2);
        cpa16(sb + chunk * 4096 + SWZ(row * 128 + seg * 16),
              g_ut16 + (size_t)gr * HH + chunk * 64 + seg * 8);
    }
    asm volatile("cp.async.commit_group;" ::: "memory");

    // gate-math ownership: thread -> (b, j)
    const int gb = tid >> 3;                 // 0..31
    const int gj = tid & 7;                  // 0..7
    float creg = c0[gb * HH + jbase + gj];

    asm volatile("cp.async.wait_group 0;" ::: "memory");
    __syncthreads();

    for (int t = 0; t < TT; t++) {
        // ---- load A = h(t-1) fp16 [32][1024] into swizzled smem
        const __half* hsrc = (t == 0) ? g_h016
                                      : (g_hs_h + (size_t)(t - 1) * (BB * HH));
#pragma unroll
        for (int it = 0; it < 16; it++) {
            int u = it * 256 + tid;
            int chunk = u >> 8;
            int rem = u & 255;
            int row = rem >> 3, seg = rem & 7;
            cpa16(sb + 65536 + chunk * 4096 + SWZ(row * 128 + seg * 16),
                  hsrc + (size_t)row * HH + chunk * 64 + seg * 8);
        }
        asm volatile("cp.async.commit_group;" ::: "memory");
        asm volatile("cp.async.wait_group 0;" ::: "memory");
        __syncthreads();

        // ---- MMA: warp wid handles k-chunks {2w, 2w+1}
        float acc[2][4][4];
#pragma unroll
        for (int mi = 0; mi < 2; mi++)
#pragma unroll
            for (int ni = 0; ni < 4; ni++)
#pragma unroll
                for (int k = 0; k < 4; k++) acc[mi][ni][k] = 0.0f;

#pragma unroll
        for (int cc = 0; cc < 2; cc++) {
            const uint32_t ab = sb + 65536 + (2 * wid + cc) * 4096;
            const uint32_t bb = sb + (2 * wid + cc) * 4096;
#pragma unroll
            for (int kss = 0; kss < 4; kss++) {
                uint32_t a[2][4];
#pragma unroll
                for (int mi = 0; mi < 2; mi++) {
                    int row = mi * 16 + (l & 15);
                    int un  = kss * 2 + (l >> 4);
                    uint32_t addr = ab + SWZ(row * 128 + un * 16);
                    asm volatile("ldmatrix.sync.aligned.m8n8.x4.shared.b16 {%0,%1,%2,%3}, [%4];"
                                 : "=r"(a[mi][0]), "=r"(a[mi][1]), "=r"(a[mi][2]), "=r"(a[mi][3])
                                 : "r"(addr));
                }
                uint32_t bf[2][4];
#pragma unroll
                for (int nb = 0; nb < 2; nb++) {
                    int row = nb * 16 + ((l >> 4) << 3) + (l & 7);
                    int un  = kss * 2 + ((l >> 3) & 1);
                    uint32_t addr = bb + SWZ(row * 128 + un * 16);
                    asm volatile("ldmatrix.sync.aligned.m8n8.x4.shared.b16 {%0,%1,%2,%3}, [%4];"
                                 : "=r"(bf[nb][0]), "=r"(bf[nb][1]), "=r"(bf[nb][2]), "=r"(bf[nb][3])
                                 : "r"(addr));
                }
#pragma unroll
                for (int mi = 0; mi < 2; mi++)
#pragma unroll
                    for (int ni = 0; ni < 4; ni++) {
                        uint32_t b0 = bf[ni >> 1][(ni & 1) * 2 + 0];
                        uint32_t b1 = bf[ni >> 1][(ni & 1) * 2 + 1];
                        asm volatile(
                            "mma.sync.aligned.m16n8k16.row.col.f32.f16.f16.f32 "
                            "{%0,%1,%2,%3}, {%4,%5,%6,%7}, {%8,%9}, {%0,%1,%2,%3};"
                            : "+f"(acc[mi][ni][0]), "+f"(acc[mi][ni][1]),
                              "+f"(acc[mi][ni][2]), "+f"(acc[mi][ni][3])
                            : "r"(a[mi][0]), "r"(a[mi][1]), "r"(a[mi][2]), "r"(a[mi][3]),
                              "r"(b0), "r"(b1));
                    }
            }
        }

        // ---- write K-partials: zred[w][b][n], pitch 36 (bank/LDS.128 clean)
        {
            float* zw = zred + wid * 1152;
#pragma unroll
            for (int mi = 0; mi < 2; mi++)
#pragma unroll
                for (int ni = 0; ni < 4; ni++) {
                    int r = mi * 16 + (l >> 2);
                    int c = ni * 8 + (l & 3) * 2;
                    *(float2*)&zw[r * 36 + c] =
                        make_float2(acc[mi][ni][0], acc[mi][ni][1]);
                    *(float2*)&zw[(r + 8) * 36 + c] =
                        make_float2(acc[mi][ni][2], acc[mi][ni][3]);
                }
        }
        __syncthreads();

        // ---- gate math: thread (gb, gj); n = gj*4+g -> float4 = (i,f,g,o)
        {
            float4 zs = make_float4(0.f, 0.f, 0.f, 0.f);
#pragma unroll
            for (int w = 0; w < 8; w++) {
                float4 v = *(const float4*)&zred[w * 1152 + gb * 36 + (gj << 2)];
                zs.x += v.x; zs.y += v.y; zs.z += v.z; zs.w += v.w;
            }
            const float* xb = g_xz + (size_t)t * BB * GG + (size_t)gb * GG;
            const int j = jbase + gj;
            float zi = zs.x + xb[j];
            float zf = zs.y + xb[HH + j];
            float zg = zs.z + xb[2 * HH + j];
            float zo = zs.w + xb[3 * HH + j];
            float cn = sigm(zf) * creg + sigm(zi) * tanhf(zg);
            float hn = sigm(zo) * tanhf(cn);
            creg = cn;
            g_hs_h[(size_t)t * BB * HH + (size_t)gb * HH + j] = __float2half(hn);
        }

        // ---- global step barrier (volatile poll; RMW only on arrival)
        __threadfence();
        __syncthreads();
        if (tid == 0) {
            atomicAdd(&g_bar, 1u);
            const unsigned target = 128u * (unsigned)(t + 1);
            volatile unsigned* vb = &g_bar;
            while (*vb < target) { }
        }
        __syncthreads();
    }
}

// ---------------------------------------------------------------------------
extern "C" void kernel_launch(void* const* d_in, const int* in_sizes, int n_in,
                              void* d_out, int out_size)
{
    const int*   X     = (const int*)  d_in[0];
    const float* h0    = (const float*)d_in[1];
    const float* c0    = (const float*)d_in[2];
    const float* emb   = (const float*)d_in[3];
    const float* W     = (const float*)d_in[4];
    const float* U     = (const float*)d_in[5];
    const float* b     = (const float*)d_in[6];
    const float* Wd    = (const float*)d_in[7];
    const float* bd    = (const float*)d_in[8];
    const float* gamma = (const float*)d_in[9];
    const float* beta  = (const float*)d_in[10];
    const float* mmean = (const float*)d_in[11];
    const float* mvar  = (const float*)d_in[12];
    float* out = (float*)d_out;

    cudaFuncSetAttribute(lstm_mma_kernel,
                         cudaFuncAttributeMaxDynamicSharedMemorySize, 167936);
    cudaFuncSetAttribute(mma_epi_kernel<512, false>,
                         cudaFuncAttributeMaxDynamicSharedMemorySize, 66560);
    cudaFuncSetAttribute(mma_epi_kernel<1024, true>,
                         cudaFuncAttributeMaxDynamicSharedMemorySize, 66560);

    init_bar_kernel<<<1, 1>>>();

    // preps
    gather_conv_kernel<<<MM, 128>>>(X, emb);
    wt_conv_kernel<<<dim3(GG / 32, EE / 32), 256>>>(W);
    ut_conv_kernel<<<dim3(GG / 32, HH / 32), 256>>>(U);
    wd_split_kernel<<<dim3(VV / 32, HH / 32), 256>>>(Wd);
    h0_conv_kernel<<<(BB * HH) / 256, 256>>>(h0);

    // Xz = emb[X]@W + b  (HMMA fp16; writes g_xz internally)
    mma_epi_kernel<512, false><<<dim3(GG / 128, MM / 128), 256, 66560>>>(
        b, nullptr, nullptr, nullptr, nullptr, nullptr, GG);

    // persistent HMMA LSTM over all 128 steps
    lstm_mma_kernel<<<128, 256, 167936>>>(c0);

    // projection + BN (HMMA fp16)
    mma_epi_kernel<1024, true><<<dim3(VV / 128, MM / 128), 256, 66560>>>(
        bd, gamma, beta, mmean, mvar, out, VV);
}

// round 13
// speedup vs baseline: 4.7065x; 1.2139x over previous
#include <cuda_runtime.h>
#include <cuda_fp16.h>
#include <math.h>
#include <stdint.h>

// Shapes (fixed): B=32, T=128, V=32000, E=512, H=1024, 4H=4096
#define BB 32
#define TT 128
#define VV 32000
#define EE 512
#define HH 1024
#define GG 4096
#define MM 4096   // T*B rows

// ------------------------- static device scratch ---------------------------
__device__ float  g_xz[(size_t)MM * GG];        // emb[X]@W + b  (64 MB)
__device__ __half g_hs_h[(size_t)MM * HH];      // hs fp16 archive (8 MB) — also h state
__device__ __half g_h016[BB * HH];              // h0 fp16
__device__ __half g_wdt_h[(size_t)VV * HH];     // Wd^T fp16 [V][K] (64 MB)
__device__ __half g_a16[(size_t)MM * EE];       // gathered emb fp16 (4 MB)
__device__ __half g_wt16[(size_t)GG * EE];      // W^T fp16 [4H][E] (4 MB)
__device__ __half g_ut16[(size_t)GG * HH];      // U^T fp16 [4H][H] (8 MB)
__device__ unsigned g_bar;                      // persistent-kernel barrier

__device__ __forceinline__ float sigm(float x) { return 1.0f / (1.0f + expf(-x)); }

__device__ __forceinline__ uint32_t smem_u32(const void* p) {
    uint32_t a;
    asm("{ .reg .u64 t; cvta.to.shared.u64 t, %1; cvt.u32.u64 %0, t; }"
        : "=r"(a) : "l"(p));
    return a;
}
__device__ __forceinline__ void cpa16(uint32_t d, const void* s) {
    asm volatile("cp.async.cg.shared.global [%0], [%1], 16;" :: "r"(d), "l"(s));
}
#define SWZ(x) ((x) ^ (((x) >> 3) & 0x70))

// ---------------------------------------------------------------------------
__global__ void init_bar_kernel() { g_bar = 0u; }

// ---------------------------------------------------------------------------
// Prep A: gather emb rows -> fp16, row r = t*32+b
// ---------------------------------------------------------------------------
__global__ void __launch_bounds__(128) gather_conv_kernel(
    const int* __restrict__ X, const float* __restrict__ emb)
{
    const int r = blockIdx.x;
    const int t = r >> 5, b = r & 31;
    const int e = X[b * TT + t];
    float4 v = ((const float4*)(emb + (size_t)e * EE))[threadIdx.x];
    __half2 h01 = __floats2half2_rn(v.x, v.y);
    __half2 h23 = __floats2half2_rn(v.z, v.w);
    uint2 pk;
    pk.x = *(uint32_t*)&h01;
    pk.y = *(uint32_t*)&h23;
    *(uint2*)(g_a16 + (size_t)r * EE + threadIdx.x * 4) = pk;
}

// ---------------------------------------------------------------------------
// Prep B: W [E=512][4H] -> W^T fp16 [4H][E]
// ---------------------------------------------------------------------------
__global__ void __launch_bounds__(256) wt_conv_kernel(const float* __restrict__ W)
{
    __shared__ float tb[32][33];
    const int n0 = blockIdx.x * 32;
    const int k0 = blockIdx.y * 32;
    const int tx = threadIdx.x & 31;
    const int ty0 = threadIdx.x >> 5;
#pragma unroll
    for (int ty = ty0; ty < 32; ty += 8)
        tb[ty][tx] = W[(size_t)(k0 + ty) * GG + n0 + tx];
    __syncthreads();
#pragma unroll
    for (int ty = ty0; ty < 32; ty += 8)
        g_wt16[(size_t)(n0 + ty) * EE + k0 + tx] = __float2half(tb[tx][ty]);
}

// ---------------------------------------------------------------------------
// Prep B2: U [H=1024][4H] -> U^T fp16 [4H][H]
// ---------------------------------------------------------------------------
__global__ void __launch_bounds__(256) ut_conv_kernel(const float* __restrict__ U)
{
    __shared__ float tb[32][33];
    const int n0 = blockIdx.x * 32;
    const int k0 = blockIdx.y * 32;
    const int tx = threadIdx.x & 31;
    const int ty0 = threadIdx.x >> 5;
#pragma unroll
    for (int ty = ty0; ty < 32; ty += 8)
        tb[ty][tx] = U[(size_t)(k0 + ty) * GG + n0 + tx];
    __syncthreads();
#pragma unroll
    for (int ty = ty0; ty < 32; ty += 8)
        g_ut16[(size_t)(n0 + ty) * HH + k0 + tx] = __float2half(tb[tx][ty]);
}

// ---------------------------------------------------------------------------
// Prep C: Wd [K=1024][V] -> Wd^T fp16 [V][K]
// ---------------------------------------------------------------------------
__global__ void __launch_bounds__(256) wd_split_kernel(const float* __restrict__ Wd)
{
    __shared__ float tb[32][33];
    const int v0 = blockIdx.x * 32;
    const int k0 = blockIdx.y * 32;
    const int tx = threadIdx.x & 31;
    const int ty0 = threadIdx.x >> 5;
#pragma unroll
    for (int ty = ty0; ty < 32; ty += 8)
        tb[ty][tx] = Wd[(size_t)(k0 + ty) * VV + v0 + tx];
    __syncthreads();
#pragma unroll
    for (int ty = ty0; ty < 32; ty += 8)
        g_wdt_h[(size_t)(v0 + ty) * HH + k0 + tx] = __float2half(tb[tx][ty]);
}

// ---------------------------------------------------------------------------
// Prep D: h0 fp32 -> fp16
// ---------------------------------------------------------------------------
__global__ void __launch_bounds__(256) h0_conv_kernel(const float* __restrict__ h0)
{
    int i = blockIdx.x * 256 + threadIdx.x;
    g_h016[i] = __float2half(h0[i]);
}

// ---------------------------------------------------------------------------
// Templated HMMA GEMM + epilogue.  Occ=2 CTAs/SM for latency hiding:
//   BN=false: A=g_a16 [M][512],  B=g_wt16 [4096][512],  out=g_xz (+bias)
//   BN=true : A=g_hs_h [M][1024],B=g_wdt_h [V][1024],   out=outp (BN epi)
// ---------------------------------------------------------------------------
template <int KD, bool BN>
__global__ void __launch_bounds__(256, 2) mma_epi_kernel(
    const float* __restrict__ bias, const float* __restrict__ gamma,
    const float* __restrict__ beta, const float* __restrict__ mmean,
    const float* __restrict__ mvar, float* __restrict__ outp, int ldo)
{
    extern __shared__ char smem[];
    const int tid = threadIdx.x;
    const int wid = tid >> 5, l = tid & 31;
    const int wr = wid & 3, wc = wid >> 2;
    const int m0 = blockIdx.y << 7;
    const int n0 = blockIdx.x << 7;
    constexpr int CH = KD / 64;

    const __half* Ag0 = BN ? g_hs_h : g_a16;
    const __half* Bg0 = BN ? g_wdt_h : g_wt16;
    float* op = BN ? outp : g_xz;

    float* sc = (float*)(smem + 65536);
    float* sf = (float*)(smem + 66048);
    if (tid < 128) {
        int n = n0 + tid;
        float scv = 1.0f, sfv = bias[n];
        if (BN) {
            float iv = gamma[n] * rsqrtf(mvar[n] + 1e-3f);
            scv = iv;
            sfv = beta[n] + (bias[n] - mmean[n]) * iv;
        }
        sc[tid] = scv;
        sf[tid] = sfv;
    }

    const uint32_t sb = smem_u32(smem);
    const __half* Ag = Ag0 + (size_t)m0 * KD;
    const __half* Bg = Bg0 + (size_t)n0 * KD;

    auto load_chunk = [&](int c) {
        const int k0 = c << 6;
        const uint32_t base = sb + (c & 1) * 32768;
#pragma unroll
        for (int q = 0; q < 4; q++) {
            int u = q * 256 + tid;
            int row = u >> 3, un = u & 7;
            uint32_t off = SWZ(row * 128 + un * 16);
            cpa16(base + off,         Ag + (size_t)row * KD + k0 + un * 8);
            cpa16(base + 16384 + off, Bg + (size_t)row * KD + k0 + un * 8);
        }
        asm volatile("cp.async.commit_group;" ::: "memory");
    };

    float acc[2][8][4];
#pragma unroll
    for (int mi = 0; mi < 2; mi++)
#pragma unroll
        for (int ni = 0; ni < 8; ni++)
#pragma unroll
            for (int k = 0; k < 4; k++) acc[mi][ni][k] = 0.0f;

    load_chunk(0);
    load_chunk(1);

    for (int c = 0; c < CH; c++) {
        if (c < CH - 1) asm volatile("cp.async.wait_group 1;" ::: "memory");
        else            asm volatile("cp.async.wait_group 0;" ::: "memory");
        __syncthreads();

        const uint32_t base = sb + (c & 1) * 32768;
#pragma unroll
        for (int kss = 0; kss < 4; kss++) {
            uint32_t a[2][4];
#pragma unroll
            for (int mi = 0; mi < 2; mi++) {
                int row = wr * 32 + mi * 16 + (l & 15);
                int un  = kss * 2 + (l >> 4);
                uint32_t addr = base + SWZ(row * 128 + un * 16);
                asm volatile("ldmatrix.sync.aligned.m8n8.x4.shared.b16 {%0,%1,%2,%3}, [%4];"
                             : "=r"(a[mi][0]), "=r"(a[mi][1]), "=r"(a[mi][2]), "=r"(a[mi][3])
                             : "r"(addr));
            }
            uint32_t bf[4][4];
#pragma unroll
            for (int nb = 0; nb < 4; nb++) {
                int row = wc * 64 + nb * 16 + ((l >> 4) << 3) + (l & 7);
                int un  = kss * 2 + ((l >> 3) & 1);
                uint32_t addr = base + 16384 + SWZ(row * 128 + un * 16);
                asm volatile("ldmatrix.sync.aligned.m8n8.x4.shared.b16 {%0,%1,%2,%3}, [%4];"
                             : "=r"(bf[nb][0]), "=r"(bf[nb][1]), "=r"(bf[nb][2]), "=r"(bf[nb][3])
                             : "r"(addr));
            }
#pragma unroll
            for (int mi = 0; mi < 2; mi++)
#pragma unroll
                for (int ni = 0; ni < 8; ni++) {
                    uint32_t b0 = bf[ni >> 1][(ni & 1) * 2 + 0];
                    uint32_t b1 = bf[ni >> 1][(ni & 1) * 2 + 1];
                    asm volatile(
                        "mma.sync.aligned.m16n8k16.row.col.f32.f16.f16.f32 "
                        "{%0,%1,%2,%3}, {%4,%5,%6,%7}, {%8,%9}, {%0,%1,%2,%3};"
                        : "+f"(acc[mi][ni][0]), "+f"(acc[mi][ni][1]),
                          "+f"(acc[mi][ni][2]), "+f"(acc[mi][ni][3])
                        : "r"(a[mi][0]), "r"(a[mi][1]), "r"(a[mi][2]), "r"(a[mi][3]),
                          "r"(b0), "r"(b1));
                }
        }
        __syncthreads();
        if (c + 2 < CH) load_chunk(c + 2);
    }

#pragma unroll
    for (int mi = 0; mi < 2; mi++) {
        int r0 = m0 + wr * 32 + mi * 16 + (l >> 2);
#pragma unroll
        for (int ni = 0; ni < 8; ni++) {
            int cl = wc * 64 + ni * 8 + (l & 3) * 2;
            float s0 = sc[cl], s1 = sc[cl + 1];
            float f0 = sf[cl], f1 = sf[cl + 1];
            float2 v0 = make_float2(acc[mi][ni][0] * s0 + f0,
                                    acc[mi][ni][1] * s1 + f1);
            float2 v1 = make_float2(acc[mi][ni][2] * s0 + f0,
                                    acc[mi][ni][3] * s1 + f1);
            *(float2*)(op + (size_t)r0 * ldo + n0 + cl) = v0;
            *(float2*)(op + (size_t)(r0 + 8) * ldo + n0 + cl) = v1;
        }
    }
}

// ---------------------------------------------------------------------------
// Persistent LSTM v3 (HMMA, unchanged from R12): 128 CTAs, 256 threads.
// Dyn smem: U 65536 + A 65536 + zred 36864 -> 167936 B.
// ---------------------------------------------------------------------------
__global__ void __launch_bounds__(256, 1) lstm_mma_kernel(const float* __restrict__ c0)
{
    extern __shared__ char sm[];
    const uint32_t sb = smem_u32(sm);
    float* zred = (float*)(sm + 131072);     // [8][32][36] fp32, padded

    const int tid = threadIdx.x;
    const int wid = tid >> 5, l = tid & 31;
    const int jbase = blockIdx.x * 8;

    // ---- stage U^T slice once: local row n -> global row (n&3)*1024+jbase+(n>>2)
#pragma unroll
    for (int it = 0; it < 16; it++) {
        int u = it * 256 + tid;              // 0..4095
        int chunk = u >> 8;
        int rem = u & 255;
        int row = rem >> 3, seg = rem & 7;
        int gr = (row & 3) * 1024 + jbase + (row >> 2);
        cpa16(sb + chunk * 4096 + SWZ(row * 128 + seg * 16),
              g_ut16 + (size_t)gr * HH + chunk * 64 + seg * 8);
    }
    asm volatile("cp.async.commit_group;" ::: "memory");

    const int gb = tid >> 3;                 // 0..31
    const int gj = tid & 7;                  // 0..7
    float creg = c0[gb * HH + jbase + gj];

    asm volatile("cp.async.wait_group 0;" ::: "memory");
    __syncthreads();

    for (int t = 0; t < TT; t++) {
        const __half* hsrc = (t == 0) ? g_h016
                                      : (g_hs_h + (size_t)(t - 1) * (BB * HH));
#pragma unroll
        for (int it = 0; it < 16; it++) {
            int u = it * 256 + tid;
            int chunk = u >> 8;
            int rem = u & 255;
            int row = rem >> 3, seg = rem & 7;
            cpa16(sb + 65536 + chunk * 4096 + SWZ(row * 128 + seg * 16),
                  hsrc + (size_t)row * HH + chunk * 64 + seg * 8);
        }
        asm volatile("cp.async.commit_group;" ::: "memory");
        asm volatile("cp.async.wait_group 0;" ::: "memory");
        __syncthreads();

        float acc[2][4][4];
#pragma unroll
        for (int mi = 0; mi < 2; mi++)
#pragma unroll
            for (int ni = 0; ni < 4; ni++)
#pragma unroll
                for (int k = 0; k < 4; k++) acc[mi][ni][k] = 0.0f;

#pragma unroll
        for (int cc = 0; cc < 2; cc++) {
            const uint32_t ab = sb + 65536 + (2 * wid + cc) * 4096;
            const uint32_t bb = sb + (2 * wid + cc) * 4096;
#pragma unroll
            for (int kss = 0; kss < 4; kss++) {
                uint32_t a[2][4];
#pragma unroll
                for (int mi = 0; mi < 2; mi++) {
                    int row = mi * 16 + (l & 15);
                    int un  = kss * 2 + (l >> 4);
                    uint32_t addr = ab + SWZ(row * 128 + un * 16);
                    asm volatile("ldmatrix.sync.aligned.m8n8.x4.shared.b16 {%0,%1,%2,%3}, [%4];"
                                 : "=r"(a[mi][0]), "=r"(a[mi][1]), "=r"(a[mi][2]), "=r"(a[mi][3])
                                 : "r"(addr));
                }
                uint32_t bf[2][4];
#pragma unroll
                for (int nb = 0; nb < 2; nb++) {
                    int row = nb * 16 + ((l >> 4) << 3) + (l & 7);
                    int un  = kss * 2 + ((l >> 3) & 1);
                    uint32_t addr = bb + SWZ(row * 128 + un * 16);
                    asm volatile("ldmatrix.sync.aligned.m8n8.x4.shared.b16 {%0,%1,%2,%3}, [%4];"
                                 : "=r"(bf[nb][0]), "=r"(bf[nb][1]), "=r"(bf[nb][2]), "=r"(bf[nb][3])
                                 : "r"(addr));
                }
#pragma unroll
                for (int mi = 0; mi < 2; mi++)
#pragma unroll
                    for (int ni = 0; ni < 4; ni++) {
                        uint32_t b0 = bf[ni >> 1][(ni & 1) * 2 + 0];
                        uint32_t b1 = bf[ni >> 1][(ni & 1) * 2 + 1];
                        asm volatile(
                            "mma.sync.aligned.m16n8k16.row.col.f32.f16.f16.f32 "
                            "{%0,%1,%2,%3}, {%4,%5,%6,%7}, {%8,%9}, {%0,%1,%2,%3};"
                            : "+f"(acc[mi][ni][0]), "+f"(acc[mi][ni][1]),
                              "+f"(acc[mi][ni][2]), "+f"(acc[mi][ni][3])
                            : "r"(a[mi][0]), "r"(a[mi][1]), "r"(a[mi][2]), "r"(a[mi][3]),
                              "r"(b0), "r"(b1));
                    }
            }
        }

        {
            float* zw = zred + wid * 1152;
#pragma unroll
            for (int mi = 0; mi < 2; mi++)
#pragma unroll
                for (int ni = 0; ni < 4; ni++) {
                    int r = mi * 16 + (l >> 2);
                    int c = ni * 8 + (l & 3) * 2;
                    *(float2*)&zw[r * 36 + c] =
                        make_float2(acc[mi][ni][0], acc[mi][ni][1]);
                    *(float2*)&zw[(r + 8) * 36 + c] =
                        make_float2(acc[mi][ni][2], acc[mi][ni][3]);
                }
        }
        __syncthreads();

        {
            float4 zs = make_float4(0.f, 0.f, 0.f, 0.f);
#pragma unroll
            for (int w = 0; w < 8; w++) {
                float4 v = *(const float4*)&zred[w * 1152 + gb * 36 + (gj << 2)];
                zs.x += v.x; zs.y += v.y; zs.z += v.z; zs.w += v.w;
            }
            const float* xb = g_xz + (size_t)t * BB * GG + (size_t)gb * GG;
            const int j = jbase + gj;
            float zi = zs.x + xb[j];
            float zf = zs.y + xb[HH + j];
            float zg = zs.z + xb[2 * HH + j];
            float zo = zs.w + xb[3 * HH + j];
            float cn = sigm(zf) * creg + sigm(zi) * tanhf(zg);
            float hn = sigm(zo) * tanhf(cn);
            creg = cn;
            g_hs_h[(size_t)t * BB * HH + (size_t)gb * HH + j] = __float2half(hn);
        }

        __threadfence();
        __syncthreads();
        if (tid == 0) {
            atomicAdd(&g_bar, 1u);
            const unsigned target = 128u * (unsigned)(t + 1);
            volatile unsigned* vb = &g_bar;
            while (*vb < target) { }
        }
        __syncthreads();
    }
}

// ---------------------------------------------------------------------------
extern "C" void kernel_launch(void* const* d_in, const int* in_sizes, int n_in,
                              void* d_out, int out_size)
{
    const int*   X     = (const int*)  d_in[0];
    const float* h0    = (const float*)d_in[1];
    const float* c0    = (const float*)d_in[2];
    const float* emb   = (const float*)d_in[3];
    const float* W     = (const float*)d_in[4];
    const float* U     = (const float*)d_in[5];
    const float* b     = (const float*)d_in[6];
    const float* Wd    = (const float*)d_in[7];
    const float* bd    = (const float*)d_in[8];
    const float* gamma = (const float*)d_in[9];
    const float* beta  = (const float*)d_in[10];
    const float* mmean = (const float*)d_in[11];
    const float* mvar  = (const float*)d_in[12];
    float* out = (float*)d_out;

    cudaFuncSetAttribute(lstm_mma_kernel,
                         cudaFuncAttributeMaxDynamicSharedMemorySize, 167936);
    cudaFuncSetAttribute(mma_epi_kernel<512, false>,
                         cudaFuncAttributeMaxDynamicSharedMemorySize, 66560);
    cudaFuncSetAttribute(mma_epi_kernel<1024, true>,
                         cudaFuncAttributeMaxDynamicSharedMemorySize, 66560);

    init_bar_kernel<<<1, 1>>>();

    // preps
    gather_conv_kernel<<<MM, 128>>>(X, emb);
    wt_conv_kernel<<<dim3(GG / 32, EE / 32), 256>>>(W);
    ut_conv_kernel<<<dim3(GG / 32, HH / 32), 256>>>(U);
    wd_split_kernel<<<dim3(VV / 32, HH / 32), 256>>>(Wd);
    h0_conv_kernel<<<(BB * HH) / 256, 256>>>(h0);

    // Xz = emb[X]@W + b  (HMMA fp16; writes g_xz internally)
    mma_epi_kernel<512, false><<<dim3(GG / 128, MM / 128), 256, 66560>>>(
        b, nullptr, nullptr, nullptr, nullptr, nullptr, GG);

    // persistent HMMA LSTM over all 128 steps
    lstm_mma_kernel<<<128, 256, 167936>>>(c0);

    // projection + BN (HMMA fp16)
    mma_epi_kernel<1024, true><<<dim3(VV / 128, MM / 128), 256, 66560>>>(
        bd, gamma, beta, mmean, mvar, out, VV);
}